// round 1
// baseline (speedup 1.0000x reference)
#include <cuda_runtime.h>
#include <math.h>

static constexpr int B_  = 4;
static constexpr int L_  = 2048;
static constexpr int HID = 256;   // hidden after input proj
static constexpr int DI  = 512;   // d_inner
static constexpr int NS  = 16;    // d_state
static constexpr int RK  = 16;    // dt_rank
static constexpr int NCH = 64;    // chunks
static constexpr int LC  = 32;    // chunk length (NCH*LC == L_)
static constexpr int BL  = B_ * L_;   // 8192

// ---------------- scratch (device globals; no allocations allowed) ----------------
__device__ __align__(256) float g_h  [BL * HID];            // input-proj output
__device__ __align__(256) float g_xz [2 * BL * 2 * DI];     // per-dir xz (xi | z)
__device__ __align__(256) float g_u  [2 * BL * DI];         // conv+silu output
__device__ __align__(256) float g_dbc[2 * BL * 48];         // x-proj output (dt_lr|B|C)
__device__ __align__(256) float g_dt [2 * BL * DI];         // softplus dt
__device__ __align__(256) float g_S  [2 * NCH * B_ * DI * NS];
__device__ __align__(256) float g_P  [2 * NCH * B_ * DI * NS];
__device__ __align__(256) float g_Kc [2 * NCH * B_ * DI * NS];
__device__ __align__(256) float g_al [2 * NCH * B_ * DI];
__device__ __align__(256) float g_pool[2 * B_ * DI];
__device__ __align__(256) float g_embd[B_ * 2 * HID];

// ---------------- generic SGEMM: C[M,N] = A[M,K] @ W[N,K]^T (+bias) -----------
// Tiles 128x128x8, 256 threads, 8x8 per thread. M multiple of 128, K multiple of 8.
__global__ void __launch_bounds__(256, 2)
sgemm_kernel(const float* __restrict__ A, long sA,
             const float* __restrict__ Bw, long sB,
             float* __restrict__ C, long sC,
             const float* __restrict__ bias,
             int M, int N, int K)
{
    __shared__ float As[8][128];
    __shared__ float Bs[8][128];
    const int t  = threadIdx.x;
    const int tx = t & 15;
    const int ty = t >> 4;
    const long m0 = (long)blockIdx.y * 128;
    const int  n0 = blockIdx.x * 128;
    A  += (long)blockIdx.z * sA;
    Bw += (long)blockIdx.z * sB;
    C  += (long)blockIdx.z * sC;

    const int lr = t >> 1;         // 0..127
    const int lk = (t & 1) * 4;    // 0 or 4
    const float* Ap = A + (m0 + lr) * (long)K + lk;
    const bool  bv  = (n0 + lr) < N;
    const float* Bp = Bw + (long)(n0 + lr) * K + lk;

    float acc[8][8];
#pragma unroll
    for (int i = 0; i < 8; i++)
#pragma unroll
        for (int j = 0; j < 8; j++) acc[i][j] = 0.f;

    for (int k0 = 0; k0 < K; k0 += 8) {
        float4 av  = *(const float4*)(Ap + k0);
        float4 bvv = bv ? *(const float4*)(Bp + k0) : make_float4(0.f, 0.f, 0.f, 0.f);
        As[lk + 0][lr] = av.x;  As[lk + 1][lr] = av.y;
        As[lk + 2][lr] = av.z;  As[lk + 3][lr] = av.w;
        Bs[lk + 0][lr] = bvv.x; Bs[lk + 1][lr] = bvv.y;
        Bs[lk + 2][lr] = bvv.z; Bs[lk + 3][lr] = bvv.w;
        __syncthreads();
#pragma unroll
        for (int k = 0; k < 8; k++) {
            float4 a0 = *(const float4*)&As[k][ty * 8];
            float4 a1 = *(const float4*)&As[k][ty * 8 + 4];
            float4 b0 = *(const float4*)&Bs[k][tx * 8];
            float4 b1 = *(const float4*)&Bs[k][tx * 8 + 4];
            float ar[8] = {a0.x, a0.y, a0.z, a0.w, a1.x, a1.y, a1.z, a1.w};
            float br[8] = {b0.x, b0.y, b0.z, b0.w, b1.x, b1.y, b1.z, b1.w};
#pragma unroll
            for (int i = 0; i < 8; i++)
#pragma unroll
                for (int j = 0; j < 8; j++)
                    acc[i][j] = fmaf(ar[i], br[j], acc[i][j]);
        }
        __syncthreads();
    }

#pragma unroll
    for (int i = 0; i < 8; i++) {
        long m = m0 + ty * 8 + i;
#pragma unroll
        for (int j = 0; j < 8; j++) {
            int n = n0 + tx * 8 + j;
            if (n < N) {
                float v = acc[i][j];
                if (bias) v += bias[n];
                C[m * (long)N + n] = v;
            }
        }
    }
}

// ---------------- depthwise causal conv (dir-aware) + silu --------------------
__global__ void conv_silu_kernel(const float* __restrict__ cw, const float* __restrict__ cb)
{
    int t = blockIdx.x * blockDim.x + threadIdx.x;   // 2*B*L*DI = 2^23
    int d   = t & (DI - 1);
    int l   = (t >> 9) & (L_ - 1);
    int b   = (t >> 20) & 3;
    int dir = (t >> 22) & 1;
    const float* xi = g_xz + (size_t)dir * BL * 2 * DI;   // xi = first DI cols
    const float* w  = cw + (dir * DI + d) * 4;
    float acc = cb[dir * DI + d];
    if (dir == 0) {
#pragma unroll
        for (int k = 0; k < 4; k++) {
            int ll = l - 3 + k;
            if (ll >= 0) acc = fmaf(w[k], xi[((size_t)b * L_ + ll) * (2 * DI) + d], acc);
        }
    } else {
#pragma unroll
        for (int k = 0; k < 4; k++) {
            int ll = l + 3 - k;
            if (ll < L_) acc = fmaf(w[k], xi[((size_t)b * L_ + ll) * (2 * DI) + d], acc);
        }
    }
    float uvv = acc / (1.f + __expf(-acc));   // silu
    g_u[(size_t)dir * BL * DI + ((size_t)b * L_ + l) * DI + d] = uvv;
}

// ---------------- dt = softplus(dt_lr @ dt_w^T + dt_b) (K=16 matvec fused) ----
__global__ void dt_kernel(const float* __restrict__ dt_w, const float* __restrict__ dt_b)
{
    int t = blockIdx.x * blockDim.x + threadIdx.x;
    int d   = t & (DI - 1);
    int l   = (t >> 9) & (L_ - 1);
    int b   = (t >> 20) & 3;
    int dir = (t >> 22) & 1;
    const float* row = g_dbc + (size_t)dir * BL * 48 + ((size_t)b * L_ + l) * 48;
    const float* w   = dt_w + (size_t)(dir * DI + d) * RK;
    float s = dt_b[dir * DI + d];
#pragma unroll
    for (int r = 0; r < RK; r++) s = fmaf(row[r], w[r], s);
    float dt = (s > 15.f) ? s : log1pf(__expf(s));
    g_dt[(size_t)dir * BL * DI + ((size_t)b * L_ + l) * DI + d] = dt;
}

// ---------------- chunked selective scan, pass 1 ------------------------------
// One thread per (dir, b, chunk, d). Produces per-chunk: local state S, decay
// product P, pooled local contribution accl, and correction weights K[n] so
// that the pooled output needs NO second pass over the sequence.
__global__ void __launch_bounds__(128)
scan1_kernel(const float* __restrict__ A_log, const float* __restrict__ Dp)
{
    int bid = blockIdx.x;                 // 2048 = 2*4*64*4
    int dq  = bid & 3;
    int c   = (bid >> 2) & (NCH - 1);
    int b   = (bid >> 8) & 3;
    int dir = bid >> 10;
    int d   = dq * 128 + threadIdx.x;

    const float* dtp = g_dt  + (size_t)dir * BL * DI;
    const float* up  = g_u   + (size_t)dir * BL * DI;
    const float* zp  = g_xz  + (size_t)dir * BL * 2 * DI + DI;   // z half
    const float* dbp = g_dbc + (size_t)dir * BL * 48;

    float a[NS];
#pragma unroll
    for (int n = 0; n < NS; n++) a[n] = -__expf(A_log[(size_t)(dir * DI + d) * NS + n]);
    const float Dv = Dp[dir * DI + d];

    float h[NS], pp[NS], Kk[NS];
#pragma unroll
    for (int n = 0; n < NS; n++) { h[n] = 0.f; pp[n] = 1.f; Kk[n] = 0.f; }
    float accl = 0.f;

    for (int j = 0; j < LC; j++) {
        int s = c * LC + j;
        int l = dir ? (L_ - 1 - s) : s;
        size_t base = (size_t)b * L_ + l;
        float dtv = dtp[base * DI + d];
        float uv  = up [base * DI + d];
        float zv  = zp [base * 2 * DI + d];
        float gate = zv / (1.f + __expf(-zv));
        float x = dtv * uv;

        const float4* bc4 = (const float4*)(dbp + base * 48 + 16);
        float4 q0 = bc4[0], q1 = bc4[1], q2 = bc4[2], q3 = bc4[3];   // B
        float4 q4 = bc4[4], q5 = bc4[5], q6 = bc4[6], q7 = bc4[7];   // C
        float Bn[NS] = {q0.x, q0.y, q0.z, q0.w, q1.x, q1.y, q1.z, q1.w,
                        q2.x, q2.y, q2.z, q2.w, q3.x, q3.y, q3.z, q3.w};
        float Cn[NS] = {q4.x, q4.y, q4.z, q4.w, q5.x, q5.y, q5.z, q5.w,
                        q6.x, q6.y, q6.z, q6.w, q7.x, q7.y, q7.z, q7.w};

        float yl = 0.f;
#pragma unroll
        for (int n = 0; n < NS; n++) {
            float dA = __expf(dtv * a[n]);
            h[n]  = fmaf(dA, h[n], x * Bn[n]);
            pp[n] *= dA;
            yl    = fmaf(h[n], Cn[n], yl);
            Kk[n] = fmaf(gate * Cn[n], pp[n], Kk[n]);
        }
        accl = fmaf(gate, fmaf(uv, Dv, yl), accl);
    }

    size_t r = (((size_t)dir * NCH + c) * B_ + b) * DI + d;
    g_al[r] = accl;
#pragma unroll
    for (int n = 0; n < NS; n++) {
        g_S [r * NS + n] = h[n];
        g_P [r * NS + n] = pp[n];
        g_Kc[r * NS + n] = Kk[n];
    }
}

// ---------------- scan combine: stitch chunks, produce pooled sums ------------
__global__ void scan2_kernel()
{
    int idx = blockIdx.x * blockDim.x + threadIdx.x;   // 2*B*DI = 4096
    if (idx >= 2 * B_ * DI) return;
    int dir = idx >> 11;
    int rem = idx & 2047;
    int b = rem >> 9;
    int d = rem & (DI - 1);
    float hin[NS];
#pragma unroll
    for (int n = 0; n < NS; n++) hin[n] = 0.f;
    float acc = 0.f;
    for (int c = 0; c < NCH; c++) {
        size_t r = (((size_t)dir * NCH + c) * B_ + b) * DI + d;
        acc += g_al[r];
#pragma unroll
        for (int n = 0; n < NS; n++) acc = fmaf(hin[n], g_Kc[r * NS + n], acc);
#pragma unroll
        for (int n = 0; n < NS; n++) hin[n] = fmaf(g_P[r * NS + n], hin[n], g_S[r * NS + n]);
    }
    g_pool[idx] = acc;   // sum over t of gated y, per (dir,b,d)
}

// ---------------- head: pooled @ out_w^T (per dir) -> embd --------------------
__global__ void head1_kernel(const float* __restrict__ out_w)
{
    int idx = blockIdx.x * blockDim.x + threadIdx.x;   // B * 512 = 2048
    if (idx >= B_ * 2 * HID) return;
    int b = idx >> 9;
    int cf = idx & 511;
    int dir = cf >> 8;
    int cc = cf & (HID - 1);
    const float* pr = g_pool + dir * B_ * DI + b * DI;
    const float* wr = out_w + ((size_t)dir * HID + cc) * DI;
    float s = 0.f;
#pragma unroll 8
    for (int k = 0; k < DI; k++) s = fmaf(pr[k], wr[k], s);
    g_embd[b * 512 + cf] = s * (1.f / (float)L_);
}

// ---------------- head: embd @ op_w^T + op_b ----------------------------------
__global__ void head2_kernel(const float* __restrict__ op_w, const float* __restrict__ op_b,
                             float* __restrict__ out)
{
    int idx = blockIdx.x * blockDim.x + threadIdx.x;   // B * 256 = 1024
    if (idx >= B_ * HID) return;
    int b = idx >> 8;
    int m = idx & (HID - 1);
    const float* e = g_embd + b * 512;
    const float* w = op_w + (size_t)m * 512;
    float s = op_b[m];
#pragma unroll 8
    for (int c = 0; c < 512; c++) s = fmaf(e[c], w[c], s);
    out[b * HID + m] = s;
}

// ------------------------------------------------------------------------------
extern "C" void kernel_launch(void* const* d_in, const int* in_sizes, int n_in,
                              void* d_out, int out_size)
{
    const float* x      = (const float*)d_in[0];
    const float* ip_w   = (const float*)d_in[1];
    const float* ip_b   = (const float*)d_in[2];
    const float* in_w   = (const float*)d_in[3];
    const float* conv_w = (const float*)d_in[4];
    const float* conv_b = (const float*)d_in[5];
    const float* xproj_w= (const float*)d_in[6];
    const float* dt_w   = (const float*)d_in[7];
    const float* dt_b   = (const float*)d_in[8];
    const float* A_log  = (const float*)d_in[9];
    const float* Dp     = (const float*)d_in[10];
    const float* out_w  = (const float*)d_in[11];
    const float* op_w   = (const float*)d_in[12];
    const float* op_b   = (const float*)d_in[13];
    float* out = (float*)d_out;

    float *ph, *pxz, *pu, *pdbc;
    cudaGetSymbolAddress((void**)&ph,   g_h);
    cudaGetSymbolAddress((void**)&pxz,  g_xz);
    cudaGetSymbolAddress((void**)&pu,   g_u);
    cudaGetSymbolAddress((void**)&pdbc, g_dbc);

    dim3 blk(256);
    // 1) h = x @ ip_w^T + ip_b            [8192,512]x[256,512] -> [8192,256]
    sgemm_kernel<<<dim3(HID / 128, BL / 128, 1), blk>>>(
        x, 0, ip_w, 0, ph, 0, ip_b, BL, HID, 512);
    // 2) xz_dir = h @ in_w[dir]^T          [8192,256]x[1024,256] -> [8192,1024] x2
    sgemm_kernel<<<dim3(1024 / 128, BL / 128, 2), blk>>>(
        ph, 0, in_w, (long)1024 * HID, pxz, (long)BL * 1024, nullptr, BL, 1024, HID);
    // 3) u = silu(depthwise causal conv(xi) + cb), dir-aware time orientation
    conv_silu_kernel<<<(2 * BL * DI) / 256, 256>>>(conv_w, conv_b);
    // 4) dbc = u @ xproj_w[dir]^T          [8192,512]x[48,512] -> [8192,48] x2
    sgemm_kernel<<<dim3(1, BL / 128, 2), blk>>>(
        pu, (long)BL * DI, xproj_w, (long)48 * 512, pdbc, (long)BL * 48, nullptr, BL, 48, 512);
    // 5) dt = softplus(dt_lr @ dt_w^T + dt_b)
    dt_kernel<<<(2 * BL * DI) / 256, 256>>>(dt_w, dt_b);
    // 6) chunked scan pass 1 (both dirs, fused gating + pooling terms)
    scan1_kernel<<<2048, 128>>>(A_log, Dp);
    // 7) chunk combine -> pooled sums
    scan2_kernel<<<16, 256>>>();
    // 8) pooled @ out_w^T (mean folded), concat dirs -> embd
    head1_kernel<<<8, 256>>>(out_w);
    // 9) embd @ op_w^T + op_b -> out
    head2_kernel<<<4, 256>>>(op_w, op_b, out);
}